// round 16
// baseline (speedup 1.0000x reference)
#include <cuda_runtime.h>
#include <cuda_fp16.h>
#include <cstdint>
#include <math.h>

#define BB   64
#define CIN  256
#define HID  256
#define TT   512
#define G4   1024   // 4*HID

// ---------------- scratch (__device__ globals) ------------------------------
__device__ float g_wx[(size_t)TT * BB * G4];      // [t][b][col]  128 MiB
__device__ uint4 g_wA[(size_t)BB * 2 * 16 * 512]; // own-k block
__device__ uint4 g_wB[(size_t)BB * 2 * 16 * 512]; // peer-k block

// column slot lc in [0,512) -> global gate column (R10/R12 map).
__device__ __forceinline__ int gcol(int lc, int half) {
    int th   = lc & 255;
    int sel  = lc >> 8;
    int role = th & 1;
    int j    = th >> 1;
    int g    = sel * 2 + role;
    return g * 256 + half * 128 + j;
}

// MUFU tanh.approx activations (accuracy-proven in R15)
__device__ __forceinline__ float tanh_a(float x) {
    float y;
    asm("tanh.approx.f32 %0, %1;" : "=f"(y) : "f"(x));
    return y;
}
__device__ __forceinline__ float sig_a(float x) {    // sigma(x) = 0.5 + 0.5*tanh(x/2)
    return fmaf(tanh_a(0.5f * x), 0.5f, 0.5f);
}

// ---------------- conv: W_hh fp32 -> fp16 blobs ------------------------------
__global__ __launch_bounds__(256) void conv_whh_kernel(const float* __restrict__ Whh) {
    int t    = blockIdx.x * 256 + threadIdx.x;
    int lc   = t & 511;
    int k8   = (t >> 9) & 15;
    int half = (t >> 13) & 1;
    int b    = t >> 14;
    int col  = gcol(lc, half);
    {
        int kg0 = half * 128 + k8 * 8;
        const float* s = Whh + ((size_t)b * HID + kg0) * G4 + col;
        __half hx[8];
        #pragma unroll
        for (int i = 0; i < 8; i++) hx[i] = __float2half(s[(size_t)i * G4]);
        g_wA[t] = *(uint4*)hx;
    }
    {
        int kg0 = (1 - half) * 128 + k8 * 8;
        const float* s = Whh + ((size_t)b * HID + kg0) * G4 + col;
        __half hx[8];
        #pragma unroll
        for (int i = 0; i < 8; i++) hx[i] = __float2half(s[(size_t)i * G4]);
        g_wB[t] = *(uint4*)hx;
    }
}

// ---------------- phase 1: HMMA GEMM, k-major staging + ldmatrix (R14) ------
__device__ __forceinline__ void mma16816(float* d, const uint32_t* a, const uint32_t* bf) {
    asm volatile(
        "mma.sync.aligned.m16n8k16.row.col.f32.f16.f16.f32 "
        "{%0,%1,%2,%3}, {%4,%5,%6,%7}, {%8,%9}, {%0,%1,%2,%3};"
        : "+f"(d[0]), "+f"(d[1]), "+f"(d[2]), "+f"(d[3])
        : "r"(a[0]), "r"(a[1]), "r"(a[2]), "r"(a[3]), "r"(bf[0]), "r"(bf[1]));
}

__device__ __forceinline__ void ldsm_x4_t(uint32_t* r, uint32_t saddr) {
    asm volatile(
        "ldmatrix.sync.aligned.m8n8.x4.trans.shared.b16 {%0,%1,%2,%3}, [%4];"
        : "=r"(r[0]), "=r"(r[1]), "=r"(r[2]), "=r"(r[3]) : "r"(saddr));
}

#define LDB 136   // 128 + 8 halves pad -> 272B rows, LDSM-conflict-free

__global__ __launch_bounds__(256) void wx_hmma_kernel(
    const float* __restrict__ x,     // [B][CIN][T]
    const float* __restrict__ Wih,   // [B][CIN][4H]
    const float* __restrict__ bh)    // [B][1][4H]
{
    __shared__ __half As[32 * LDB];   // [k_local][t_local]
    __shared__ __half Bs[32 * LDB];   // [k_local][n_local]

    const int tid  = threadIdx.x;
    const int m0   = blockIdx.x * 128;
    const int n0   = blockIdx.y * 128;
    const int b    = blockIdx.z;
    const int wid  = tid >> 5, lane = tid & 31;
    const int wm   = (wid & 1) * 64, wn = (wid >> 1) * 32;
    const int g    = lane >> 2, tig = lane & 3;

    float acc[4][4][4];
    #pragma unroll
    for (int i = 0; i < 4; i++)
        #pragma unroll
        for (int j = 0; j < 4; j++)
            #pragma unroll
            for (int r = 0; r < 4; r++) acc[i][j][r] = 0.0f;

    const float* xb = x   + (size_t)b * CIN * TT + m0;
    const float* wb = Wih + (size_t)b * CIN * G4 + n0;

    const int lane7 = lane & 7;
    const int aK = ((lane >> 4) & 1) * 8 + lane7;
    const int aT = ((lane >> 3) & 1) * 8;
    const int bK = ((lane >> 3) & 1) * 8 + lane7;
    const int bN = ((lane >> 4) & 1) * 8;
    const uint32_t asBase = (uint32_t)__cvta_generic_to_shared(As)
                          + (uint32_t)((aK * LDB + wm + aT) * 2);
    const uint32_t bsBase = (uint32_t)__cvta_generic_to_shared(Bs)
                          + (uint32_t)((bK * LDB + wn + bN) * 2);

    #pragma unroll 1
    for (int kb = 0; kb < CIN; kb += 32) {
        #pragma unroll
        for (int i = 0; i < 4; i++) {
            int idx = tid + i * 256;
            int k = idx >> 5, tq = idx & 31;
            float4 v = *(const float4*)(xb + (size_t)(kb + k) * TT + tq * 4);
            __half2 lo = __floats2half2_rn(v.x, v.y);
            __half2 hi = __floats2half2_rn(v.z, v.w);
            uint2 pk = { *(uint32_t*)&lo, *(uint32_t*)&hi };
            *(uint2*)(As + k * LDB + tq * 4) = pk;
        }
        #pragma unroll
        for (int i = 0; i < 4; i++) {
            int idx = tid + i * 256;
            int k = idx >> 5, nq = idx & 31;
            float4 v = *(const float4*)(wb + (size_t)(kb + k) * G4 + nq * 4);
            __half2 lo = __floats2half2_rn(v.x, v.y);
            __half2 hi = __floats2half2_rn(v.z, v.w);
            uint2 pk = { *(uint32_t*)&lo, *(uint32_t*)&hi };
            *(uint2*)(Bs + k * LDB + nq * 4) = pk;
        }
        __syncthreads();

        #pragma unroll
        for (int ks = 0; ks < 2; ks++) {
            const uint32_t ksOff = (uint32_t)(ks * 16 * LDB * 2);
            uint32_t a[4][4], bf[4][2];
            #pragma unroll
            for (int mf = 0; mf < 4; mf++)
                ldsm_x4_t(a[mf], asBase + ksOff + (uint32_t)(mf * 16 * 2));
            #pragma unroll
            for (int nf2 = 0; nf2 < 2; nf2++) {
                uint32_t bb[4];
                ldsm_x4_t(bb, bsBase + ksOff + (uint32_t)(nf2 * 16 * 2));
                bf[2 * nf2][0]     = bb[0];
                bf[2 * nf2][1]     = bb[1];
                bf[2 * nf2 + 1][0] = bb[2];
                bf[2 * nf2 + 1][1] = bb[3];
            }
            #pragma unroll
            for (int mf = 0; mf < 4; mf++)
                #pragma unroll
                for (int nf = 0; nf < 4; nf++)
                    mma16816(acc[mf][nf], a[mf], bf[nf]);
        }
        __syncthreads();
    }

    #pragma unroll
    for (int nf = 0; nf < 4; nf++) {
        int col = n0 + wn + nf * 8 + tig * 2;
        float2 bias = *(const float2*)(bh + (size_t)b * G4 + col);
        #pragma unroll
        for (int mf = 0; mf < 4; mf++) {
            int t0 = m0 + wm + mf * 16 + g;
            float2 v0 = { acc[mf][nf][0] + bias.x, acc[mf][nf][1] + bias.y };
            float2 v1 = { acc[mf][nf][2] + bias.x, acc[mf][nf][3] + bias.y };
            *(float2*)(g_wx + ((size_t)t0 * BB + b) * G4 + col) = v0;
            *(float2*)(g_wx + ((size_t)(t0 + 8) * BB + b) * G4 + col) = v1;
        }
    }
}

// ---------------- phase 2: recurrence (R15 + 4-way split chains) ------------
#define SMEM_W_BYTES  (8 * 512 * 16)                  // 65536
#define SMEM_HS_OFF   SMEM_W_BYTES
#define SMEM_FLAG_OFF (SMEM_HS_OFF + 2 * 128 * 4)
#define SMEM_TOTAL_R  (SMEM_FLAG_OFF + 16)            // 66576 B

__global__ void __cluster_dims__(2, 1, 1) __launch_bounds__(256, 1)
lstm_rec_kernel(const float* __restrict__ h0,
                const float* __restrict__ c0,
                float* __restrict__ out)
{
    extern __shared__ char smem[];
    uint4*   w_s  = (uint4*)smem;                     // peer chunks 8..15
    __half2* hs2  = (__half2*)(smem + SMEM_HS_OFF);

    const int tid    = threadIdx.x;
    const int b      = blockIdx.x >> 1;
    const int half   = blockIdx.x & 1;
    const int HALF16 = half * 16;
    const int PEER16 = 16 - HALF16;
    const int role   = tid & 1;
    const int j      = tid >> 1;

    uint4 wregA[16], wregB[16], wregPA[8], wregPB[8];
    const uint4* gwa = g_wA + ((size_t)(b * 2 + half) << 13);
    #pragma unroll
    for (int a = 0; a < 16; a++) {
        wregA[a] = gwa[a * 512 + tid];
        wregB[a] = gwa[a * 512 + tid + 256];
    }
    const uint4* gwb = g_wB + ((size_t)(b * 2 + half) << 13);
    #pragma unroll
    for (int a = 0; a < 8; a++) {
        wregPA[a] = gwb[a * 512 + tid];
        wregPB[a] = gwb[a * 512 + tid + 256];
    }
    #pragma unroll
    for (int a = 8; a < 16; a++) {
        w_s[(a - 8) * 512 + tid]       = gwb[a * 512 + tid];
        w_s[(a - 8) * 512 + tid + 256] = gwb[a * 512 + tid + 256];
    }

    float c = c0[b * HID + half * 128 + j];
    if (tid < 128)
        hs2[tid] = __floats2half2_rn(h0[b * HID + 2 * tid],
                                     h0[b * HID + 2 * tid + 1]);
    if (tid == 0)
        *(volatile uint32_t*)(smem + SMEM_FLAG_OFF) = 0;
    __syncthreads();
    asm volatile("barrier.cluster.arrive.aligned;\n\t"
                 "barrier.cluster.wait.aligned;" ::: "memory");

    const uint32_t smemBase   = (uint32_t)__cvta_generic_to_shared(smem);
    const uint32_t hsAddrBase = smemBase + SMEM_HS_OFF;
    const uint32_t flagAddr   = smemBase + SMEM_FLAG_OFF;
    const uint32_t peerRank   = (uint32_t)(half ^ 1);
    uint32_t rHsBase, rFlag;
    asm volatile("mapa.shared::cluster.u32 %0, %1, %2;"
                 : "=r"(rHsBase) : "r"(hsAddrBase), "r"(peerRank));
    asm volatile("mapa.shared::cluster.u32 %0, %1, %2;"
                 : "=r"(rFlag) : "r"(flagAddr), "r"(peerRank));

    const int colA = gcol(tid, half);
    const float* wxA_ptr = g_wx + (size_t)b * G4 + colA;
    const float* wxB_ptr = wxA_ptr + 512;

    float wxA = __ldg(wxA_ptr);
    float wxB = __ldg(wxB_ptr);
    const __half2 hz = __float2half2_rn(0.0f);

    #pragma unroll 1
    for (int t = 0; t < TT; t++) {
        const int p = t & 1;

        float nxA = wxA, nxB = wxB;
        if (t + 1 < TT) {
            size_t off = (size_t)(t + 1) * (BB * G4);
            nxA = __ldg(wxA_ptr + off);
            nxB = __ldg(wxB_ptr + off);
        }

        float accA = wxA, accB = wxB;
        const __half2* hsp = hs2 + p * 128;

        // ---- phase A: own-k, 4 independent chains per column ----
        {
            __half2 s0 = hz, s1 = hz, s2 = hz, s3 = hz;   // col A chains
            __half2 r0 = hz, r1 = hz, r2 = hz, r3 = hz;   // col B chains
            #pragma unroll
            for (int q = 0; q < 4; q++) {
                #pragma unroll
                for (int i = 0; i < 4; i++) {
                    int a  = q * 4 + i;
                    int k8 = HALF16 + a;
                    uint4 hv = *(const uint4*)(hsp + k8 * 4);
                    __half2 h01 = *(__half2*)&hv.x, h23 = *(__half2*)&hv.y;
                    __half2 h45 = *(__half2*)&hv.z, h67 = *(__half2*)&hv.w;
                    uint4 wa = wregA[a], wb = wregB[a];
                    __half2 &sa = (i == 0) ? s0 : (i == 1) ? s1 : (i == 2) ? s2 : s3;
                    __half2 &rb = (i == 0) ? r0 : (i == 1) ? r1 : (i == 2) ? r2 : r3;
                    sa = __hfma2(h01, *(__half2*)&wa.x, sa);
                    sa = __hfma2(h23, *(__half2*)&wa.y, sa);
                    sa = __hfma2(h45, *(__half2*)&wa.z, sa);
                    sa = __hfma2(h67, *(__half2*)&wa.w, sa);
                    rb = __hfma2(h01, *(__half2*)&wb.x, rb);
                    rb = __hfma2(h23, *(__half2*)&wb.y, rb);
                    rb = __hfma2(h45, *(__half2*)&wb.z, rb);
                    rb = __hfma2(h67, *(__half2*)&wb.w, rb);
                }
            }
            __half2 sA = __hadd2(__hadd2(s0, s1), __hadd2(s2, s3));
            __half2 sB = __hadd2(__hadd2(r0, r1), __hadd2(r2, r3));
            float2 fa = __half22float2(sA); accA += fa.x + fa.y;
            float2 fb = __half22float2(sB); accB += fb.x + fb.y;
        }

        if (t) {
            uint32_t v;
            do {
                asm volatile("ld.acquire.cluster.shared::cta.b32 %0, [%1];"
                             : "=r"(v) : "r"(flagAddr) : "memory");
            } while ((int)v < t);
        }

        // ---- phase B: peer-k, 4 independent chains per column ----
        {
            __half2 s0 = hz, s1 = hz, s2 = hz, s3 = hz;
            __half2 r0 = hz, r1 = hz, r2 = hz, r3 = hz;
            #pragma unroll
            for (int q = 0; q < 4; q++) {
                #pragma unroll
                for (int i = 0; i < 4; i++) {
                    int bi = q * 4 + i;
                    int k8 = PEER16 + bi;
                    uint4 hv = *(const uint4*)(hsp + k8 * 4);
                    __half2 h01 = *(__half2*)&hv.x, h23 = *(__half2*)&hv.y;
                    __half2 h45 = *(__half2*)&hv.z, h67 = *(__half2*)&hv.w;
                    uint4 wa, wb;
                    if (bi < 8) { wa = wregPA[bi]; wb = wregPB[bi]; }
                    else {
                        wa = w_s[(bi - 8) * 512 + tid];
                        wb = w_s[(bi - 8) * 512 + tid + 256];
                    }
                    __half2 &sa = (i == 0) ? s0 : (i == 1) ? s1 : (i == 2) ? s2 : s3;
                    __half2 &rb = (i == 0) ? r0 : (i == 1) ? r1 : (i == 2) ? r2 : r3;
                    sa = __hfma2(h01, *(__half2*)&wa.x, sa);
                    sa = __hfma2(h23, *(__half2*)&wa.y, sa);
                    sa = __hfma2(h45, *(__half2*)&wa.z, sa);
                    sa = __hfma2(h67, *(__half2*)&wa.w, sa);
                    rb = __hfma2(h01, *(__half2*)&wb.x, rb);
                    rb = __hfma2(h23, *(__half2*)&wb.y, rb);
                    rb = __hfma2(h45, *(__half2*)&wb.z, rb);
                    rb = __hfma2(h67, *(__half2*)&wb.w, rb);
                }
            }
            __half2 sA = __hadd2(__hadd2(s0, s1), __hadd2(s2, s3));
            __half2 sB = __hadd2(__hadd2(r0, r1), __hadd2(r2, r3));
            float2 fa = __half22float2(sA); accA += fa.x + fa.y;
            float2 fb = __half22float2(sB); accB += fb.x + fb.y;
        }

        // ---- tail with MUFU tanh.approx (R15) ----
        float ga = tanh_a(accA);
        float gb = tanh_a(accB);
        float gax = __shfl_xor_sync(0xffffffffu, ga, 1);
        float gbx = __shfl_xor_sync(0xffffffffu, gb, 1);

        float ti = role ? gax : ga;
        float tf = role ? ga  : gax;
        float tg = role ? gbx : gb;
        float to = role ? gb  : gbx;

        c = c * sig_a(tf) + sig_a(ti) * tanh_a(tg);
        float hn = sig_a(to) * tanh_a(c);

        if (role)
            out[((size_t)(b * HID + half * 128 + j)) * TT + t] = hn;

        float ho = __shfl_xor_sync(0xffffffffu, hn, 2);
        if ((tid & 3) == 0) {
            __half2 hp = __floats2half2_rn(hn, ho);
            int k2 = half * 64 + (tid >> 2);
            uint32_t off = (uint32_t)(((p ^ 1) * 128 + k2) * 4);
            hs2[(p ^ 1) * 128 + k2] = hp;
            if (t + 1 < TT)
                asm volatile("st.shared::cluster.u32 [%0], %1;"
                             :: "r"(rHsBase + off), "r"(*(uint32_t*)&hp) : "memory");
        }
        __syncthreads();

        if (tid == 0 && t + 1 < TT) {
            asm volatile("fence.acq_rel.cluster;" ::: "memory");
            asm volatile("st.relaxed.cluster.shared::cluster.b32 [%0], %1;"
                         :: "r"(rFlag), "r"(t + 1) : "memory");
        }

        wxA = nxA; wxB = nxB;
    }

    if (role)
        out[(size_t)BB * HID * TT + b * HID + half * 128 + j] = c;

    asm volatile("barrier.cluster.arrive.aligned;\n\t"
                 "barrier.cluster.wait.aligned;" ::: "memory");
}

// ---------------- launch ------------------------------------------------------
extern "C" void kernel_launch(void* const* d_in, const int* in_sizes, int n_in,
                              void* d_out, int out_size) {
    const float* x   = (const float*)d_in[0];
    const float* h0  = (const float*)d_in[1];
    const float* c0  = (const float*)d_in[2];
    const float* Wih = (const float*)d_in[3];
    const float* Whh = (const float*)d_in[4];
    const float* bh  = (const float*)d_in[5];
    float* out = (float*)d_out;

    cudaFuncSetAttribute(lstm_rec_kernel,
                         cudaFuncAttributeMaxDynamicSharedMemorySize, SMEM_TOTAL_R);

    conv_whh_kernel<<<(BB * 2 * 16 * 512) / 256, 256>>>(Whh);

    wx_hmma_kernel<<<dim3(TT / 128, G4 / 128, BB), 256>>>(x, Wih, bh);

    lstm_rec_kernel<<<2 * BB, 256, SMEM_TOTAL_R>>>(h0, c0, out);

    (void)in_sizes; (void)n_in; (void)out_size;
}

// round 17
// speedup vs baseline: 1.1541x; 1.1541x over previous
#include <cuda_runtime.h>
#include <cuda_fp16.h>
#include <cstdint>
#include <math.h>

#define BB   64
#define CIN  256
#define HID  256
#define TT   512
#define G4   1024   // 4*HID

// ---------------- scratch (__device__ globals) ------------------------------
__device__ float g_wx[(size_t)TT * BB * G4];      // [t][b][col]  128 MiB
__device__ uint4 g_wA[(size_t)BB * 2 * 16 * 512]; // own-k block
__device__ uint4 g_wB[(size_t)BB * 2 * 16 * 512]; // peer-k block

// column slot lc in [0,512) -> global gate column (R10/R12 map).
__device__ __forceinline__ int gcol(int lc, int half) {
    int th   = lc & 255;
    int sel  = lc >> 8;
    int role = th & 1;
    int j    = th >> 1;
    int g    = sel * 2 + role;
    return g * 256 + half * 128 + j;
}

// MUFU tanh.approx activations (accuracy-proven in R15)
__device__ __forceinline__ float tanh_a(float x) {
    float y;
    asm("tanh.approx.f32 %0, %1;" : "=f"(y) : "f"(x));
    return y;
}
__device__ __forceinline__ float sig_a(float x) {    // sigma(x) = 0.5 + 0.5*tanh(x/2)
    return fmaf(tanh_a(0.5f * x), 0.5f, 0.5f);
}

// ---------------- conv: W_hh fp32 -> fp16 blobs ------------------------------
__global__ __launch_bounds__(256) void conv_whh_kernel(const float* __restrict__ Whh) {
    int t    = blockIdx.x * 256 + threadIdx.x;
    int lc   = t & 511;
    int k8   = (t >> 9) & 15;
    int half = (t >> 13) & 1;
    int b    = t >> 14;
    int col  = gcol(lc, half);
    {
        int kg0 = half * 128 + k8 * 8;
        const float* s = Whh + ((size_t)b * HID + kg0) * G4 + col;
        __half hx[8];
        #pragma unroll
        for (int i = 0; i < 8; i++) hx[i] = __float2half(s[(size_t)i * G4]);
        g_wA[t] = *(uint4*)hx;
    }
    {
        int kg0 = (1 - half) * 128 + k8 * 8;
        const float* s = Whh + ((size_t)b * HID + kg0) * G4 + col;
        __half hx[8];
        #pragma unroll
        for (int i = 0; i < 8; i++) hx[i] = __float2half(s[(size_t)i * G4]);
        g_wB[t] = *(uint4*)hx;
    }
}

// ---------------- phase 1: HMMA GEMM, k-major staging + ldmatrix (R14) ------
__device__ __forceinline__ void mma16816(float* d, const uint32_t* a, const uint32_t* bf) {
    asm volatile(
        "mma.sync.aligned.m16n8k16.row.col.f32.f16.f16.f32 "
        "{%0,%1,%2,%3}, {%4,%5,%6,%7}, {%8,%9}, {%0,%1,%2,%3};"
        : "+f"(d[0]), "+f"(d[1]), "+f"(d[2]), "+f"(d[3])
        : "r"(a[0]), "r"(a[1]), "r"(a[2]), "r"(a[3]), "r"(bf[0]), "r"(bf[1]));
}

__device__ __forceinline__ void ldsm_x4_t(uint32_t* r, uint32_t saddr) {
    asm volatile(
        "ldmatrix.sync.aligned.m8n8.x4.trans.shared.b16 {%0,%1,%2,%3}, [%4];"
        : "=r"(r[0]), "=r"(r[1]), "=r"(r[2]), "=r"(r[3]) : "r"(saddr));
}

#define LDB 136   // 128 + 8 halves pad -> 272B rows, LDSM-conflict-free

__global__ __launch_bounds__(256) void wx_hmma_kernel(
    const float* __restrict__ x,     // [B][CIN][T]
    const float* __restrict__ Wih,   // [B][CIN][4H]
    const float* __restrict__ bh)    // [B][1][4H]
{
    __shared__ __half As[32 * LDB];   // [k_local][t_local]
    __shared__ __half Bs[32 * LDB];   // [k_local][n_local]

    const int tid  = threadIdx.x;
    const int m0   = blockIdx.x * 128;
    const int n0   = blockIdx.y * 128;
    const int b    = blockIdx.z;
    const int wid  = tid >> 5, lane = tid & 31;
    const int wm   = (wid & 1) * 64, wn = (wid >> 1) * 32;
    const int g    = lane >> 2, tig = lane & 3;

    float acc[4][4][4];
    #pragma unroll
    for (int i = 0; i < 4; i++)
        #pragma unroll
        for (int j = 0; j < 4; j++)
            #pragma unroll
            for (int r = 0; r < 4; r++) acc[i][j][r] = 0.0f;

    const float* xb = x   + (size_t)b * CIN * TT + m0;
    const float* wb = Wih + (size_t)b * CIN * G4 + n0;

    const int lane7 = lane & 7;
    const int aK = ((lane >> 4) & 1) * 8 + lane7;
    const int aT = ((lane >> 3) & 1) * 8;
    const int bK = ((lane >> 3) & 1) * 8 + lane7;
    const int bN = ((lane >> 4) & 1) * 8;
    const uint32_t asBase = (uint32_t)__cvta_generic_to_shared(As)
                          + (uint32_t)((aK * LDB + wm + aT) * 2);
    const uint32_t bsBase = (uint32_t)__cvta_generic_to_shared(Bs)
                          + (uint32_t)((bK * LDB + wn + bN) * 2);

    #pragma unroll 1
    for (int kb = 0; kb < CIN; kb += 32) {
        #pragma unroll
        for (int i = 0; i < 4; i++) {
            int idx = tid + i * 256;
            int k = idx >> 5, tq = idx & 31;
            float4 v = *(const float4*)(xb + (size_t)(kb + k) * TT + tq * 4);
            __half2 lo = __floats2half2_rn(v.x, v.y);
            __half2 hi = __floats2half2_rn(v.z, v.w);
            uint2 pk = { *(uint32_t*)&lo, *(uint32_t*)&hi };
            *(uint2*)(As + k * LDB + tq * 4) = pk;
        }
        #pragma unroll
        for (int i = 0; i < 4; i++) {
            int idx = tid + i * 256;
            int k = idx >> 5, nq = idx & 31;
            float4 v = *(const float4*)(wb + (size_t)(kb + k) * G4 + nq * 4);
            __half2 lo = __floats2half2_rn(v.x, v.y);
            __half2 hi = __floats2half2_rn(v.z, v.w);
            uint2 pk = { *(uint32_t*)&lo, *(uint32_t*)&hi };
            *(uint2*)(Bs + k * LDB + nq * 4) = pk;
        }
        __syncthreads();

        #pragma unroll
        for (int ks = 0; ks < 2; ks++) {
            const uint32_t ksOff = (uint32_t)(ks * 16 * LDB * 2);
            uint32_t a[4][4], bf[4][2];
            #pragma unroll
            for (int mf = 0; mf < 4; mf++)
                ldsm_x4_t(a[mf], asBase + ksOff + (uint32_t)(mf * 16 * 2));
            #pragma unroll
            for (int nf2 = 0; nf2 < 2; nf2++) {
                uint32_t bb[4];
                ldsm_x4_t(bb, bsBase + ksOff + (uint32_t)(nf2 * 16 * 2));
                bf[2 * nf2][0]     = bb[0];
                bf[2 * nf2][1]     = bb[1];
                bf[2 * nf2 + 1][0] = bb[2];
                bf[2 * nf2 + 1][1] = bb[3];
            }
            #pragma unroll
            for (int mf = 0; mf < 4; mf++)
                #pragma unroll
                for (int nf = 0; nf < 4; nf++)
                    mma16816(acc[mf][nf], a[mf], bf[nf]);
        }
        __syncthreads();
    }

    #pragma unroll
    for (int nf = 0; nf < 4; nf++) {
        int col = n0 + wn + nf * 8 + tig * 2;
        float2 bias = *(const float2*)(bh + (size_t)b * G4 + col);
        #pragma unroll
        for (int mf = 0; mf < 4; mf++) {
            int t0 = m0 + wm + mf * 16 + g;
            float2 v0 = { acc[mf][nf][0] + bias.x, acc[mf][nf][1] + bias.y };
            float2 v1 = { acc[mf][nf][2] + bias.x, acc[mf][nf][3] + bias.y };
            *(float2*)(g_wx + ((size_t)t0 * BB + b) * G4 + col) = v0;
            *(float2*)(g_wx + ((size_t)(t0 + 8) * BB + b) * G4 + col) = v1;
        }
    }
}

// ---------------- phase 2: recurrence (R15 base; ALL peer chunks in SMEM) ---
#define SMEM_W_BYTES  (16 * 512 * 16)                 // 131072: peer chunks 0..15
#define SMEM_HS_OFF   SMEM_W_BYTES
#define SMEM_FLAG_OFF (SMEM_HS_OFF + 2 * 128 * 4)
#define SMEM_TOTAL_R  (SMEM_FLAG_OFF + 16)            // 132112 B

__global__ void __cluster_dims__(2, 1, 1) __launch_bounds__(256, 1)
lstm_rec_kernel(const float* __restrict__ h0,
                const float* __restrict__ c0,
                float* __restrict__ out)
{
    extern __shared__ char smem[];
    uint4*   w_s  = (uint4*)smem;                     // peer chunks 0..15
    __half2* hs2  = (__half2*)(smem + SMEM_HS_OFF);

    const int tid    = threadIdx.x;
    const int b      = blockIdx.x >> 1;
    const int half   = blockIdx.x & 1;
    const int HALF16 = half * 16;
    const int PEER16 = 16 - HALF16;
    const int role   = tid & 1;
    const int j      = tid >> 1;

    // weight residency: own 16 chunk-pairs in regs (128 regs); peer all in SMEM
    uint4 wregA[16], wregB[16];
    const uint4* gwa = g_wA + ((size_t)(b * 2 + half) << 13);
    #pragma unroll
    for (int a = 0; a < 16; a++) {
        wregA[a] = gwa[a * 512 + tid];
        wregB[a] = gwa[a * 512 + tid + 256];
    }
    const uint4* gwb = g_wB + ((size_t)(b * 2 + half) << 13);
    #pragma unroll
    for (int a = 0; a < 16; a++) {
        w_s[a * 512 + tid]       = gwb[a * 512 + tid];
        w_s[a * 512 + tid + 256] = gwb[a * 512 + tid + 256];
    }

    float c = c0[b * HID + half * 128 + j];
    if (tid < 128)
        hs2[tid] = __floats2half2_rn(h0[b * HID + 2 * tid],
                                     h0[b * HID + 2 * tid + 1]);
    if (tid == 0)
        *(volatile uint32_t*)(smem + SMEM_FLAG_OFF) = 0;
    __syncthreads();
    asm volatile("barrier.cluster.arrive.aligned;\n\t"
                 "barrier.cluster.wait.aligned;" ::: "memory");

    const uint32_t smemBase   = (uint32_t)__cvta_generic_to_shared(smem);
    const uint32_t hsAddrBase = smemBase + SMEM_HS_OFF;
    const uint32_t flagAddr   = smemBase + SMEM_FLAG_OFF;
    const uint32_t peerRank   = (uint32_t)(half ^ 1);
    uint32_t rHsBase, rFlag;
    asm volatile("mapa.shared::cluster.u32 %0, %1, %2;"
                 : "=r"(rHsBase) : "r"(hsAddrBase), "r"(peerRank));
    asm volatile("mapa.shared::cluster.u32 %0, %1, %2;"
                 : "=r"(rFlag) : "r"(flagAddr), "r"(peerRank));

    const int colA = gcol(tid, half);
    const float* wxA_ptr = g_wx + (size_t)b * G4 + colA;
    const float* wxB_ptr = wxA_ptr + 512;

    float wxA = __ldg(wxA_ptr);
    float wxB = __ldg(wxB_ptr);
    const __half2 hz = __float2half2_rn(0.0f);

    #pragma unroll 1
    for (int t = 0; t < TT; t++) {
        const int p = t & 1;

        float nxA = wxA, nxB = wxB;
        if (t + 1 < TT) {
            size_t off = (size_t)(t + 1) * (BB * G4);
            nxA = __ldg(wxA_ptr + off);
            nxB = __ldg(wxB_ptr + off);
        }

        float accA = wxA, accB = wxB;
        const __half2* hsp = hs2 + p * 128;

        // ---- phase A: own-k block (register weights, local h), R15 form ----
        #pragma unroll
        for (int q = 0; q < 2; q++) {
            __half2 sA = hz, sB = hz;
            #pragma unroll
            for (int i = 0; i < 8; i++) {
                int a  = q * 8 + i;
                int k8 = HALF16 + a;
                uint4 hv = *(const uint4*)(hsp + k8 * 4);
                __half2 h01 = *(__half2*)&hv.x, h23 = *(__half2*)&hv.y;
                __half2 h45 = *(__half2*)&hv.z, h67 = *(__half2*)&hv.w;
                uint4 wa = wregA[a], wb = wregB[a];
                sA = __hfma2(h01, *(__half2*)&wa.x, sA);
                sA = __hfma2(h23, *(__half2*)&wa.y, sA);
                sA = __hfma2(h45, *(__half2*)&wa.z, sA);
                sA = __hfma2(h67, *(__half2*)&wa.w, sA);
                sB = __hfma2(h01, *(__half2*)&wb.x, sB);
                sB = __hfma2(h23, *(__half2*)&wb.y, sB);
                sB = __hfma2(h45, *(__half2*)&wb.z, sB);
                sB = __hfma2(h67, *(__half2*)&wb.w, sB);
            }
            float2 fa = __half22float2(sA); accA += fa.x + fa.y;
            float2 fb = __half22float2(sB); accB += fb.x + fb.y;
        }

        // ---- wait for peer h of this step (flag spin) ----
        if (t) {
            uint32_t v;
            do {
                asm volatile("ld.acquire.cluster.shared::cta.b32 %0, [%1];"
                             : "=r"(v) : "r"(flagAddr) : "memory");
            } while ((int)v < t);
        }

        // ---- phase B: peer-k block (ALL chunks from SMEM), R15 form ----
        #pragma unroll
        for (int q = 0; q < 2; q++) {
            __half2 sA = hz, sB = hz;
            #pragma unroll
            for (int i = 0; i < 8; i++) {
                int bi = q * 8 + i;
                int k8 = PEER16 + bi;
                uint4 hv = *(const uint4*)(hsp + k8 * 4);
                __half2 h01 = *(__half2*)&hv.x, h23 = *(__half2*)&hv.y;
                __half2 h45 = *(__half2*)&hv.z, h67 = *(__half2*)&hv.w;
                uint4 wa = w_s[bi * 512 + tid];
                uint4 wb = w_s[bi * 512 + tid + 256];
                sA = __hfma2(h01, *(__half2*)&wa.x, sA);
                sA = __hfma2(h23, *(__half2*)&wa.y, sA);
                sA = __hfma2(h45, *(__half2*)&wa.z, sA);
                sA = __hfma2(h67, *(__half2*)&wa.w, sA);
                sB = __hfma2(h01, *(__half2*)&wb.x, sB);
                sB = __hfma2(h23, *(__half2*)&wb.y, sB);
                sB = __hfma2(h45, *(__half2*)&wb.z, sB);
                sB = __hfma2(h67, *(__half2*)&wb.w, sB);
            }
            float2 fa = __half22float2(sA); accA += fa.x + fa.y;
            float2 fb = __half22float2(sB); accB += fb.x + fb.y;
        }

        // ---- tail with MUFU tanh.approx (R15) ----
        float ga = tanh_a(accA);
        float gb = tanh_a(accB);
        float gax = __shfl_xor_sync(0xffffffffu, ga, 1);
        float gbx = __shfl_xor_sync(0xffffffffu, gb, 1);

        float ti = role ? gax : ga;
        float tf = role ? ga  : gax;
        float tg = role ? gbx : gb;
        float to = role ? gb  : gbx;

        c = c * sig_a(tf) + sig_a(ti) * tanh_a(tg);
        float hn = sig_a(to) * tanh_a(c);

        if (role)
            out[((size_t)(b * HID + half * 128 + j)) * TT + t] = hn;

        float ho = __shfl_xor_sync(0xffffffffu, hn, 2);
        if ((tid & 3) == 0) {
            __half2 hp = __floats2half2_rn(hn, ho);
            int k2 = half * 64 + (tid >> 2);
            uint32_t off = (uint32_t)(((p ^ 1) * 128 + k2) * 4);
            hs2[(p ^ 1) * 128 + k2] = hp;
            if (t + 1 < TT)
                asm volatile("st.shared::cluster.u32 [%0], %1;"
                             :: "r"(rHsBase + off), "r"(*(uint32_t*)&hp) : "memory");
        }
        __syncthreads();

        if (tid == 0 && t + 1 < TT) {
            asm volatile("fence.acq_rel.cluster;" ::: "memory");
            asm volatile("st.relaxed.cluster.shared::cluster.b32 [%0], %1;"
                         :: "r"(rFlag), "r"(t + 1) : "memory");
        }

        wxA = nxA; wxB = nxB;
    }

    if (role)
        out[(size_t)BB * HID * TT + b * HID + half * 128 + j] = c;

    asm volatile("barrier.cluster.arrive.aligned;\n\t"
                 "barrier.cluster.wait.aligned;" ::: "memory");
}

// ---------------- launch ------------------------------------------------------
extern "C" void kernel_launch(void* const* d_in, const int* in_sizes, int n_in,
                              void* d_out, int out_size) {
    const float* x   = (const float*)d_in[0];
    const float* h0  = (const float*)d_in[1];
    const float* c0  = (const float*)d_in[2];
    const float* Wih = (const float*)d_in[3];
    const float* Whh = (const float*)d_in[4];
    const float* bh  = (const float*)d_in[5];
    float* out = (float*)d_out;

    cudaFuncSetAttribute(lstm_rec_kernel,
                         cudaFuncAttributeMaxDynamicSharedMemorySize, SMEM_TOTAL_R);

    conv_whh_kernel<<<(BB * 2 * 16 * 512) / 256, 256>>>(Whh);

    wx_hmma_kernel<<<dim3(TT / 128, G4 / 128, BB), 256>>>(x, Wih, bh);

    lstm_rec_kernel<<<2 * BB, 256, SMEM_TOTAL_R>>>(h0, c0, out);

    (void)in_sizes; (void)n_in; (void)out_size;
}